// round 2
// baseline (speedup 1.0000x reference)
#include <cuda_runtime.h>
#include <math.h>

#define NB 16
#define CH 3
#define HGT 512
#define WID 512
#define HW (HGT*WID)          // 262144
#define PAD 3

// Scratch: residual image (16 MB) + per-image accumulators.
__device__ float  g_R[NB*HW];
__device__ double g_S[NB];
__device__ double g_SS[NB];
__device__ double g_WR[NB];

__global__ void zero_acc_kernel() {
    int i = threadIdx.x;
    if (i < NB) { g_S[i] = 0.0; g_SS[i] = 0.0; g_WR[i] = 0.0; }
}

// ---------------------------------------------------------------------------
// Kernel 1: residual + per-image sum / sum-of-squares (for patch variance).
// One thread = 4 consecutive pixels (float4 loads). 4096 blocks x 256 thr.
// Each block lies entirely within one image (HW/4 = 65536 divisible by 256).
// ---------------------------------------------------------------------------
__global__ __launch_bounds__(256) void residual_kernel(
    const float* __restrict__ pred, const float* __restrict__ targ)
{
    const int gid = blockIdx.x * 256 + threadIdx.x;   // float4 index
    const int n   = gid / (HW/4);
    const int p4  = gid % (HW/4);

    const float4* pp = (const float4*)(pred + (size_t)n * CH * HW);
    const float4* tp = (const float4*)(targ + (size_t)n * CH * HW);

    float4 r = make_float4(0.f, 0.f, 0.f, 0.f);
    #pragma unroll
    for (int c = 0; c < CH; ++c) {
        float4 a = pp[c * (HW/4) + p4];
        float4 b = tp[c * (HW/4) + p4];
        r.x += fabsf(a.x - b.x);
        r.y += fabsf(a.y - b.y);
        r.z += fabsf(a.z - b.z);
        r.w += fabsf(a.w - b.w);
    }
    ((float4*)g_R)[(size_t)n * (HW/4) + p4] = r;

    float s  = r.x + r.y + r.z + r.w;
    float ss = r.x*r.x + r.y*r.y + r.z*r.z + r.w*r.w;

    // block reduce (256 threads = 8 warps)
    #pragma unroll
    for (int o = 16; o > 0; o >>= 1) {
        s  += __shfl_down_sync(0xffffffffu, s,  o);
        ss += __shfl_down_sync(0xffffffffu, ss, o);
    }
    __shared__ float sh_s[8], sh_ss[8];
    const int lane = threadIdx.x & 31, wid = threadIdx.x >> 5;
    if (lane == 0) { sh_s[wid] = s; sh_ss[wid] = ss; }
    __syncthreads();
    if (wid == 0) {
        s  = (lane < 8) ? sh_s[lane]  : 0.f;
        ss = (lane < 8) ? sh_ss[lane] : 0.f;
        #pragma unroll
        for (int o = 4; o > 0; o >>= 1) {
            s  += __shfl_down_sync(0xffffffffu, s,  o);
            ss += __shfl_down_sync(0xffffffffu, ss, o);
        }
        if (lane == 0) {
            atomicAdd(&g_S[n],  (double)s);
            atomicAdd(&g_SS[n], (double)ss);
        }
    }
}

// ---------------------------------------------------------------------------
// Kernel 2: local 7x7 unbiased variance (reflect pad) via separable box sums
// over shared memory, fused accumulation of pixel_w * R per image.
// Block = 32x32 threads, output tile 32x32, halo 3. Grid (16,16,16).
// ---------------------------------------------------------------------------
__device__ __forceinline__ int reflect_idx(int i, int n) {
    if (i < 0)  return -i;
    if (i >= n) return 2*n - 2 - i;
    return i;
}

__global__ __launch_bounds__(1024) void localvar_kernel()
{
    const int n  = blockIdx.z;
    const int bx = blockIdx.x * 32;
    const int by = blockIdx.y * 32;
    const int tx = threadIdx.x, ty = threadIdx.y;
    const int tid = ty * 32 + tx;

    __shared__ float  sR[38][40];     // halo tile of residual
    __shared__ float2 sH[38][33];     // horizontal box sums (sum, sumsq)

    const float* __restrict__ R = g_R + (size_t)n * HW;

    for (int i = tid; i < 38*38; i += 1024) {
        int r = i / 38, c = i % 38;
        int gy = reflect_idx(by + r - PAD, HGT);
        int gx = reflect_idx(bx + c - PAD, WID);
        sR[r][c] = R[gy * WID + gx];
    }
    __syncthreads();

    for (int i = tid; i < 38*32; i += 1024) {
        int r = i / 32, c = i % 32;
        float s = 0.f, ss = 0.f;
        #pragma unroll
        for (int k = 0; k < 7; ++k) {
            float v = sR[r][c + k];
            s += v; ss += v * v;
        }
        sH[r][c] = make_float2(s, ss);
    }
    __syncthreads();

    float s = 0.f, ss = 0.f;
    #pragma unroll
    for (int k = 0; k < 7; ++k) {
        float2 v = sH[ty + k][tx];
        s += v.x; ss += v.y;
    }
    float pixel_w = (ss - s * s * (1.0f/49.0f)) * (1.0f/48.0f);
    float contrib = pixel_w * sR[ty + PAD][tx + PAD];

    // block reduce 1024 -> 1, then one double atomicAdd per block
    #pragma unroll
    for (int o = 16; o > 0; o >>= 1)
        contrib += __shfl_down_sync(0xffffffffu, contrib, o);
    __shared__ float sh_c[32];
    const int lane = tid & 31, warp = tid >> 5;
    if (lane == 0) sh_c[warp] = contrib;
    __syncthreads();
    if (warp == 0) {
        contrib = sh_c[lane];
        #pragma unroll
        for (int o = 16; o > 0; o >>= 1)
            contrib += __shfl_down_sync(0xffffffffu, contrib, o);
        if (lane == 0) atomicAdd(&g_WR[n], (double)contrib);
    }
}

// ---------------------------------------------------------------------------
// Finalize: patch_w[n] = var_n^0.2 ; loss = sum_n patch_w*WR / (N*C*H*W)
// ---------------------------------------------------------------------------
__global__ void finalize_kernel(float* __restrict__ out)
{
    if (threadIdx.x == 0 && blockIdx.x == 0) {
        const double M = (double)HW;
        double total = 0.0;
        for (int n = 0; n < NB; ++n) {
            double var = (g_SS[n] - g_S[n] * g_S[n] / M) / (M - 1.0);
            double pw  = pow(var, 0.2);
            total += pw * g_WR[n];
        }
        out[0] = (float)(total / ((double)NB * CH * HW));
    }
}

extern "C" void kernel_launch(void* const* d_in, const int* in_sizes, int n_in,
                              void* d_out, int out_size)
{
    const float* pred = (const float*)d_in[0];
    const float* targ = (const float*)d_in[1];
    float* out = (float*)d_out;

    zero_acc_kernel<<<1, 32>>>();
    residual_kernel<<<(NB*HW/4) / 256, 256>>>(pred, targ);
    dim3 grid2(WID/32, HGT/32, NB);
    dim3 blk2(32, 32, 1);
    localvar_kernel<<<grid2, blk2>>>();
    finalize_kernel<<<1, 32>>>(out);
}

// round 3
// speedup vs baseline: 1.8496x; 1.8496x over previous
#include <cuda_runtime.h>
#include <math.h>

#define NB 16
#define CH 3
#define HGT 512
#define WID 512
#define HW (HGT*WID)          // 262144
#define PAD 3

// Scratch: residual image (16 MB) + per-image accumulators.
// Device globals are zero-initialized at module load; finalize_kernel
// re-zeroes them at the end of every call, so each graph replay starts clean.
__device__ float  g_R[NB*HW];
__device__ double g_S[NB];
__device__ double g_SS[NB];
__device__ double g_WR[NB];

// ---------------------------------------------------------------------------
// Kernel 1: residual + per-image sum / sum-of-squares (for patch variance).
// One thread = 4 consecutive pixels (float4 loads). 4096 blocks x 256 thr.
// ---------------------------------------------------------------------------
__global__ __launch_bounds__(256) void residual_kernel(
    const float* __restrict__ pred, const float* __restrict__ targ)
{
    const int gid = blockIdx.x * 256 + threadIdx.x;   // float4 index
    const int n   = gid / (HW/4);
    const int p4  = gid % (HW/4);

    const float4* pp = (const float4*)(pred + (size_t)n * CH * HW);
    const float4* tp = (const float4*)(targ + (size_t)n * CH * HW);

    float4 r = make_float4(0.f, 0.f, 0.f, 0.f);
    #pragma unroll
    for (int c = 0; c < CH; ++c) {
        float4 a = pp[c * (HW/4) + p4];
        float4 b = tp[c * (HW/4) + p4];
        r.x += fabsf(a.x - b.x);
        r.y += fabsf(a.y - b.y);
        r.z += fabsf(a.z - b.z);
        r.w += fabsf(a.w - b.w);
    }
    ((float4*)g_R)[(size_t)n * (HW/4) + p4] = r;

    float s  = r.x + r.y + r.z + r.w;
    float ss = r.x*r.x + r.y*r.y + r.z*r.z + r.w*r.w;

    #pragma unroll
    for (int o = 16; o > 0; o >>= 1) {
        s  += __shfl_down_sync(0xffffffffu, s,  o);
        ss += __shfl_down_sync(0xffffffffu, ss, o);
    }
    __shared__ float sh_s[8], sh_ss[8];
    const int lane = threadIdx.x & 31, wid = threadIdx.x >> 5;
    if (lane == 0) { sh_s[wid] = s; sh_ss[wid] = ss; }
    __syncthreads();
    if (wid == 0) {
        s  = (lane < 8) ? sh_s[lane]  : 0.f;
        ss = (lane < 8) ? sh_ss[lane] : 0.f;
        #pragma unroll
        for (int o = 4; o > 0; o >>= 1) {
            s  += __shfl_down_sync(0xffffffffu, s,  o);
            ss += __shfl_down_sync(0xffffffffu, ss, o);
        }
        if (lane == 0) {
            atomicAdd(&g_S[n],  (double)s);
            atomicAdd(&g_SS[n], (double)ss);
        }
    }
}

// ---------------------------------------------------------------------------
// Kernel 2: local 7x7 unbiased variance (reflect pad) via separable box sums
// over shared memory, fused accumulation of pixel_w * R per image.
// Block = 32x32 threads, output tile 32x32, halo 3. Grid (16,16,16).
// ---------------------------------------------------------------------------
__device__ __forceinline__ int reflect_idx(int i, int n) {
    if (i < 0)  return -i;
    if (i >= n) return 2*n - 2 - i;
    return i;
}

__global__ __launch_bounds__(1024) void localvar_kernel()
{
    const int n  = blockIdx.z;
    const int bx = blockIdx.x * 32;
    const int by = blockIdx.y * 32;
    const int tx = threadIdx.x, ty = threadIdx.y;
    const int tid = ty * 32 + tx;

    __shared__ float  sR[38][40];     // halo tile of residual
    __shared__ float2 sH[38][33];     // horizontal box sums (sum, sumsq)

    const float* __restrict__ R = g_R + (size_t)n * HW;

    for (int i = tid; i < 38*38; i += 1024) {
        int r = i / 38, c = i % 38;
        int gy = reflect_idx(by + r - PAD, HGT);
        int gx = reflect_idx(bx + c - PAD, WID);
        sR[r][c] = R[gy * WID + gx];
    }
    __syncthreads();

    for (int i = tid; i < 38*32; i += 1024) {
        int r = i / 32, c = i % 32;
        float s = 0.f, ss = 0.f;
        #pragma unroll
        for (int k = 0; k < 7; ++k) {
            float v = sR[r][c + k];
            s += v; ss += v * v;
        }
        sH[r][c] = make_float2(s, ss);
    }
    __syncthreads();

    float s = 0.f, ss = 0.f;
    #pragma unroll
    for (int k = 0; k < 7; ++k) {
        float2 v = sH[ty + k][tx];
        s += v.x; ss += v.y;
    }
    float pixel_w = (ss - s * s * (1.0f/49.0f)) * (1.0f/48.0f);
    float contrib = pixel_w * sR[ty + PAD][tx + PAD];

    #pragma unroll
    for (int o = 16; o > 0; o >>= 1)
        contrib += __shfl_down_sync(0xffffffffu, contrib, o);
    __shared__ float sh_c[32];
    const int lane = tid & 31, warp = tid >> 5;
    if (lane == 0) sh_c[warp] = contrib;
    __syncthreads();
    if (warp == 0) {
        contrib = sh_c[lane];
        #pragma unroll
        for (int o = 16; o > 0; o >>= 1)
            contrib += __shfl_down_sync(0xffffffffu, contrib, o);
        if (lane == 0) atomicAdd(&g_WR[n], (double)contrib);
    }
}

// ---------------------------------------------------------------------------
// Finalize: patch_w[n] = var_n^0.2 ; loss = sum_n patch_w*WR / (N*C*H*W).
// One warp: lane n handles image n. Variance computed in double (cancellation-
// safe), the ^0.2 in float (MUFU path, ~1e-7 rel err — plenty under 1e-3).
// Also resets the accumulators for the next graph replay.
// ---------------------------------------------------------------------------
__global__ void finalize_kernel(float* __restrict__ out)
{
    const int lane = threadIdx.x;
    const double M = (double)HW;

    double t = 0.0;
    if (lane < NB) {
        double var = (g_SS[lane] - g_S[lane] * g_S[lane] / M) / (M - 1.0);
        float  pw  = powf((float)var, 0.2f);
        t = (double)pw * g_WR[lane];
        // reset accumulators for the next replay
        g_S[lane] = 0.0; g_SS[lane] = 0.0; g_WR[lane] = 0.0;
    }
    #pragma unroll
    for (int o = 16; o > 0; o >>= 1)
        t += __shfl_down_sync(0xffffffffu, t, o);
    if (lane == 0)
        out[0] = (float)(t / ((double)NB * CH * HW));
}

extern "C" void kernel_launch(void* const* d_in, const int* in_sizes, int n_in,
                              void* d_out, int out_size)
{
    const float* pred = (const float*)d_in[0];
    const float* targ = (const float*)d_in[1];
    float* out = (float*)d_out;

    residual_kernel<<<(NB*HW/4) / 256, 256>>>(pred, targ);
    dim3 grid2(WID/32, HGT/32, NB);
    dim3 blk2(32, 32, 1);
    localvar_kernel<<<grid2, blk2>>>();
    finalize_kernel<<<1, 32>>>(out);
}

// round 4
// speedup vs baseline: 2.1436x; 1.1590x over previous
#include <cuda_runtime.h>
#include <math.h>

#define NB 16
#define CH 3
#define HGT 512
#define WID 512
#define HW (HGT*WID)          // 262144

#define TILE_W 128
#define TILE_H 64
#define HALO_W (TILE_W + 6)   // 134
#define NTHR   160            // 5 warps; 134 active columns
#define CHUNK  8

// Per-image accumulators. Zero-initialized at load; finalize re-zeroes them
// after each use so every graph replay starts clean.
__device__ double g_S[NB];
__device__ double g_SS[NB];
__device__ double g_WR[NB];

__device__ __forceinline__ int reflect_idx(int i, int n) {
    if (i < 0)  return -i;
    if (i >= n) return 2*n - 2 - i;
    return i;
}

// ---------------------------------------------------------------------------
// Fused kernel: residual (on the fly) + 7x7 local unbiased variance via
// register sliding window (vertical) + smem horizontal tap, accumulating
// per-image  S = sum(R), SS = sum(R^2), WR = sum(pixel_w * R).
// Block: 160 threads, one thread per halo column. Tile: 128x64 outputs.
// Grid: (4, 8, 16).
// ---------------------------------------------------------------------------
__global__ __launch_bounds__(NTHR) void fused_kernel(
    const float* __restrict__ pred, const float* __restrict__ targ)
{
    const int n   = blockIdx.z;
    const int bx  = blockIdx.x * TILE_W;
    const int by  = blockIdx.y * TILE_H;
    const int tid = threadIdx.x;

    __shared__ float2 sV[CHUNK][HALO_W];   // vertical window (sum, sumsq)

    const float* __restrict__ p0 = pred + (size_t)n * CH * HW;
    const float* __restrict__ t0 = targ + (size_t)n * CH * HW;

    const bool colActive = (tid < HALO_W);
    const bool isOutCol  = (tid >= 3) && (tid < 3 + TILE_W);
    const int  gx        = reflect_idx(bx + tid - 3, WID);

    float ring[7];
    float centerR[CHUNK];
    float s_acc = 0.f, ss_acc = 0.f, wr_acc = 0.f;

    // Prefill ring with logical rows by-3 .. by+2.
    if (colActive) {
        #pragma unroll
        for (int k = 0; k < 6; ++k) {
            int yr = by - 3 + k;
            int gy = reflect_idx(yr, HGT);
            int idx = gy * WID + gx;
            float r = fabsf(p0[idx]        - t0[idx])
                    + fabsf(p0[HW + idx]   - t0[HW + idx])
                    + fabsf(p0[2*HW + idx] - t0[2*HW + idx]);
            ring[k + 1] = r;
            if (isOutCol && yr >= by) { s_acc += r; ss_acc += r * r; }
        }
    }

    for (int cb = 0; cb < TILE_H; cb += CHUNK) {
        if (colActive) {
            #pragma unroll
            for (int j = 0; j < CHUNK; ++j) {
                #pragma unroll
                for (int k = 0; k < 6; ++k) ring[k] = ring[k + 1];
                const int yr = by + cb + j + 3;       // newest row
                const int gy = reflect_idx(yr, HGT);
                const int idx = gy * WID + gx;
                float r = fabsf(p0[idx]        - t0[idx])
                        + fabsf(p0[HW + idx]   - t0[HW + idx])
                        + fabsf(p0[2*HW + idx] - t0[2*HW + idx]);
                ring[6] = r;
                if (isOutCol && yr < by + TILE_H) { s_acc += r; ss_acc += r * r; }

                float s = 0.f, ss = 0.f;
                #pragma unroll
                for (int k = 0; k < 7; ++k) { s += ring[k]; ss += ring[k]*ring[k]; }
                sV[j][tid] = make_float2(s, ss);
                centerR[j] = ring[3];                 // R at output row cb+j
            }
        }
        __syncthreads();
        if (isOutCol) {
            #pragma unroll
            for (int j = 0; j < CHUNK; ++j) {
                float s = 0.f, ss = 0.f;
                #pragma unroll
                for (int k = 0; k < 7; ++k) {
                    float2 v = sV[j][tid - 3 + k];
                    s += v.x; ss += v.y;
                }
                float pw = (ss - s * s * (1.0f/49.0f)) * (1.0f/48.0f);
                wr_acc += pw * centerR[j];
            }
        }
        __syncthreads();
    }

    // Block reduce (5 warps) -> 3 double atomics per block.
    #pragma unroll
    for (int o = 16; o > 0; o >>= 1) {
        s_acc  += __shfl_down_sync(0xffffffffu, s_acc,  o);
        ss_acc += __shfl_down_sync(0xffffffffu, ss_acc, o);
        wr_acc += __shfl_down_sync(0xffffffffu, wr_acc, o);
    }
    __shared__ float red[3][5];
    const int lane = tid & 31, warp = tid >> 5;
    if (lane == 0) { red[0][warp] = s_acc; red[1][warp] = ss_acc; red[2][warp] = wr_acc; }
    __syncthreads();
    if (tid == 0) {
        float s = 0.f, ss = 0.f, wr = 0.f;
        #pragma unroll
        for (int w = 0; w < 5; ++w) { s += red[0][w]; ss += red[1][w]; wr += red[2][w]; }
        atomicAdd(&g_S[n],  (double)s);
        atomicAdd(&g_SS[n], (double)ss);
        atomicAdd(&g_WR[n], (double)wr);
    }
}

// ---------------------------------------------------------------------------
// Finalize: patch_w[n] = var_n^0.2 ; loss = sum_n patch_w*WR / (N*C*H*W).
// Lane n handles image n; resets accumulators for the next replay.
// ---------------------------------------------------------------------------
__global__ void finalize_kernel(float* __restrict__ out)
{
    const int lane = threadIdx.x;
    const double M = (double)HW;

    double t = 0.0;
    if (lane < NB) {
        double var = (g_SS[lane] - g_S[lane] * g_S[lane] / M) / (M - 1.0);
        float  pw  = powf((float)var, 0.2f);
        t = (double)pw * g_WR[lane];
        g_S[lane] = 0.0; g_SS[lane] = 0.0; g_WR[lane] = 0.0;
    }
    #pragma unroll
    for (int o = 16; o > 0; o >>= 1)
        t += __shfl_down_sync(0xffffffffu, t, o);
    if (lane == 0)
        out[0] = (float)(t / ((double)NB * CH * HW));
}

extern "C" void kernel_launch(void* const* d_in, const int* in_sizes, int n_in,
                              void* d_out, int out_size)
{
    const float* pred = (const float*)d_in[0];
    const float* targ = (const float*)d_in[1];
    float* out = (float*)d_out;

    dim3 grid(WID / TILE_W, HGT / TILE_H, NB);   // (4, 8, 16)
    fused_kernel<<<grid, NTHR>>>(pred, targ);
    finalize_kernel<<<1, 32>>>(out);
}

// round 5
// speedup vs baseline: 4.0289x; 1.8795x over previous
#include <cuda_runtime.h>
#include <math.h>

#define NB 16
#define CH 3
#define HGT 512
#define WID 512
#define HW (HGT*WID)          // 262144

#define TILE_H 8
#define NTHR   256            // 2 columns per thread -> full 512-wide rows
#define NBLOCKS (NB * (HGT / TILE_H))   // 1024

// Per-image accumulators + completion counter. Zero-initialized at load;
// the last block resets everything so each graph replay starts clean.
__device__ double   g_S[NB];
__device__ double   g_SS[NB];
__device__ double   g_WR[NB];
__device__ unsigned g_done;

__device__ __forceinline__ int reflect_idx(int i, int n) {
    if (i < 0)  return -i;
    if (i >= n) return 2*n - 2 - i;
    return i;
}

// ---------------------------------------------------------------------------
// Fully fused: residual on-the-fly + 7x7 local unbiased variance (reflect)
// + per-image S/SS/WR accumulation + final loss (last block).
// Block: 256 threads, thread t owns columns {2t, 2t+1} (float2 loads).
// Tile: full 512-wide x 8 rows. Grid: (1, 64, 16).
// Vertical 7-window: register ring. Horizontal 7-tap: smem, x-reflect free.
// ---------------------------------------------------------------------------
__global__ __launch_bounds__(NTHR, 5) void fused_kernel(
    const float* __restrict__ pred, const float* __restrict__ targ,
    float* __restrict__ out)
{
    const int n   = blockIdx.z;
    const int by  = blockIdx.y * TILE_H;
    const int tid = threadIdx.x;
    const int c0  = 2 * tid;

    __shared__ float2 sV[4][WID];        // vertical (sum, sumsq) per column
    __shared__ float  red[3][8];
    __shared__ int    sLast;

    const float* __restrict__ p0 = pred + (size_t)n * CH * HW;
    const float* __restrict__ t0 = targ + (size_t)n * CH * HW;

    float2 ring[7];                      // .x col c0, .y col c0+1
    float2 centerR[4];
    float s_acc = 0.f, ss_acc = 0.f, wr_acc = 0.f;

    // Prefill ring slots 1..6 with logical rows by-3 .. by+2.
    #pragma unroll
    for (int k = 0; k < 6; ++k) {
        const int yr = by - 3 + k;
        const int gy = reflect_idx(yr, HGT);
        const int idx = gy * WID + c0;
        float2 pa = *(const float2*)(p0 + idx);
        float2 ta = *(const float2*)(t0 + idx);
        float2 pb = *(const float2*)(p0 + HW + idx);
        float2 tb = *(const float2*)(t0 + HW + idx);
        float2 pc = *(const float2*)(p0 + 2*HW + idx);
        float2 tc = *(const float2*)(t0 + 2*HW + idx);
        float rx = fabsf(pa.x - ta.x) + fabsf(pb.x - tb.x) + fabsf(pc.x - tc.x);
        float ry = fabsf(pa.y - ta.y) + fabsf(pb.y - tb.y) + fabsf(pc.y - tc.y);
        ring[k + 1] = make_float2(rx, ry);
        if (k >= 3) {                     // rows by..by+2: count once
            s_acc  += rx + ry;
            ss_acc += rx*rx + ry*ry;
        }
    }

    #pragma unroll
    for (int phase = 0; phase < 2; ++phase) {
        #pragma unroll
        for (int j = 0; j < 4; ++j) {
            #pragma unroll
            for (int k = 0; k < 6; ++k) ring[k] = ring[k + 1];
            const int step = phase * 4 + j;
            const int yr = by + 3 + step;            // newest row
            const int gy = reflect_idx(yr, HGT);
            const int idx = gy * WID + c0;
            float2 pa = *(const float2*)(p0 + idx);
            float2 ta = *(const float2*)(t0 + idx);
            float2 pb = *(const float2*)(p0 + HW + idx);
            float2 tb = *(const float2*)(t0 + HW + idx);
            float2 pc = *(const float2*)(p0 + 2*HW + idx);
            float2 tc = *(const float2*)(t0 + 2*HW + idx);
            float rx = fabsf(pa.x - ta.x) + fabsf(pb.x - tb.x) + fabsf(pc.x - tc.x);
            float ry = fabsf(pa.y - ta.y) + fabsf(pb.y - tb.y) + fabsf(pc.y - tc.y);
            ring[6] = make_float2(rx, ry);
            if (yr < by + TILE_H) {                  // rows by+3..by+7
                s_acc  += rx + ry;
                ss_acc += rx*rx + ry*ry;
            }
            float sx = 0.f, sy = 0.f, qx = 0.f, qy = 0.f;
            #pragma unroll
            for (int k = 0; k < 7; ++k) {
                sx += ring[k].x; qx += ring[k].x * ring[k].x;
                sy += ring[k].y; qy += ring[k].y * ring[k].y;
            }
            *(float4*)&sV[j][c0] = make_float4(sx, qx, sy, qy);
            centerR[j] = ring[3];                    // R at output row by+step
        }
        __syncthreads();
        #pragma unroll
        for (int j = 0; j < 4; ++j) {
            // columns c0-3 .. c0+4 (8), reflect at image edges
            float cs[8], cq[8];
            #pragma unroll
            for (int k = 0; k < 8; ++k) {
                int cc = reflect_idx(c0 - 3 + k, WID);
                float2 v = sV[j][cc];
                cs[k] = v.x; cq[k] = v.y;
            }
            float s0 = 0.f, q0 = 0.f, s1 = 0.f, q1 = 0.f;
            #pragma unroll
            for (int k = 0; k < 7; ++k) {
                s0 += cs[k];     q0 += cq[k];
                s1 += cs[k + 1]; q1 += cq[k + 1];
            }
            float pw0 = (q0 - s0 * s0 * (1.0f/49.0f)) * (1.0f/48.0f);
            float pw1 = (q1 - s1 * s1 * (1.0f/49.0f)) * (1.0f/48.0f);
            wr_acc += pw0 * centerR[j].x + pw1 * centerR[j].y;
        }
        __syncthreads();
    }

    // Block reduce (8 warps) -> 3 double atomics.
    #pragma unroll
    for (int o = 16; o > 0; o >>= 1) {
        s_acc  += __shfl_down_sync(0xffffffffu, s_acc,  o);
        ss_acc += __shfl_down_sync(0xffffffffu, ss_acc, o);
        wr_acc += __shfl_down_sync(0xffffffffu, wr_acc, o);
    }
    const int lane = tid & 31, warp = tid >> 5;
    if (lane == 0) { red[0][warp] = s_acc; red[1][warp] = ss_acc; red[2][warp] = wr_acc; }
    __syncthreads();
    if (tid == 0) {
        float s = 0.f, ss = 0.f, wr = 0.f;
        #pragma unroll
        for (int w = 0; w < 8; ++w) { s += red[0][w]; ss += red[1][w]; wr += red[2][w]; }
        atomicAdd(&g_S[n],  (double)s);
        atomicAdd(&g_SS[n], (double)ss);
        atomicAdd(&g_WR[n], (double)wr);
        __threadfence();
        unsigned v = atomicAdd(&g_done, 1u);
        sLast = (v == NBLOCKS - 1);
    }
    __syncthreads();

    // Last block computes the loss (replaces the finalize launch).
    if (sLast && warp == 0) {
        __threadfence();
        const double M = (double)HW;
        double t = 0.0;
        if (lane < NB) {
            double S  = *(volatile double*)&g_S[lane];
            double SS = *(volatile double*)&g_SS[lane];
            double WR = *(volatile double*)&g_WR[lane];
            double var = (SS - S * S / M) / (M - 1.0);
            float  pw  = powf((float)var, 0.2f);
            t = (double)pw * WR;
            g_S[lane] = 0.0; g_SS[lane] = 0.0; g_WR[lane] = 0.0;  // reset for replay
        }
        #pragma unroll
        for (int o = 16; o > 0; o >>= 1)
            t += __shfl_down_sync(0xffffffffu, t, o);
        if (lane == 0) {
            out[0] = (float)(t / ((double)NB * CH * HW));
            g_done = 0;
        }
    }
}

extern "C" void kernel_launch(void* const* d_in, const int* in_sizes, int n_in,
                              void* d_out, int out_size)
{
    const float* pred = (const float*)d_in[0];
    const float* targ = (const float*)d_in[1];
    float* out = (float*)d_out;

    dim3 grid(1, HGT / TILE_H, NB);   // (1, 64, 16) = 1024 blocks
    fused_kernel<<<grid, NTHR>>>(pred, targ, out);
}